// round 5
// baseline (speedup 1.0000x reference)
#include <cuda_runtime.h>
#include <cuda_bf16.h>
#include <cstddef>

// Enframe: x (8,2,480000) f32 -> out (8,4096,934) f32
//   out[b, c*2048 + k, t] = x[b, c, t*512 + k]
// Decompose k = 512*q + r (q in [0,4), r in [0,512)), bc = b*2+c:
//   out[bc, q*512 + r, t] = x[bc, (t+q)*512 + r]
// Tile: 64 t x 32 r per block (small tiles -> 3840 blocks -> low wave-tail).
// Stores: float2 along t (row stride 934*4 = 3736 B, 8B-aligned).

#define S_LEN     480000
#define T_OUT     934          // (480000 - 2048)/512 + 1
#define SLOTS     937          // max slot = 933 + 3 = 936
#define ROWS      2048         // per-bc output rows
#define R_PAD     33
#define T_TILE    64
#define SLOT_NEED 67           // 64 t + q shift (3)
#define N_TTILES  15           // ceil(934/64)

__global__ __launch_bounds__(256) void enframe_kernel(const float4* __restrict__ x4,
                                                      float* __restrict__ out) {
    __shared__ float tile[SLOT_NEED * R_PAD];   // 67*33*4 = 8844 B

    const int rt = blockIdx.x;   // 0..15  r base = rt*32
    const int tt = blockIdx.y;   // 0..14  t base = tt*64
    const int bc = blockIdx.z;   // 0..15
    const int tx = threadIdx.x;  // 0..31
    const int ty = threadIdx.y;  // 0..7

    const int tb = tt * T_TILE;
    const float4* __restrict__ xin = x4 + (size_t)bc * (S_LEN / 4);

    const bool interior = (tt < N_TTILES - 1);   // tiles 0..13: no guards anywhere

    // ---- Load phase: LDG.128, scalar STS (conflict-free: rowoff+4c+j covers all banks)
    const int c      = tx & 7;          // float4 column: r = rt*32 + 4c + j
    const int rowoff = tx >> 3;         // 0..3
#pragma unroll
    for (int p = 0; p < 3; ++p) {
        const int row = p * 32 + ty * 4 + rowoff;
        if (row < SLOT_NEED) {
            const int s = tb + row;
            float4 v = make_float4(0.f, 0.f, 0.f, 0.f);
            if (interior || s < SLOTS) v = xin[(size_t)s * 128 + rt * 8 + c];
            float* dst = &tile[row * R_PAD + 4 * c];
            dst[0] = v.x; dst[1] = v.y; dst[2] = v.z; dst[3] = v.w;
        }
    }
    __syncthreads();

    // ---- Store phase: warp = (q = ty>>1, rhalf = ty&1); lane tx = t pair ----
    const int q     = ty >> 1;
    const int rhalf = ty & 1;
    const int t     = tb + 2 * tx;       // even t; pair (t, t+1)
    const int row   = 2 * tx + q;        // slot row for t (row+1 for t+1)

    const float* __restrict__ src = &tile[row * R_PAD + rhalf * 16];

    float* __restrict__ o = out + (size_t)bc * ROWS * T_OUT
                                + (size_t)(q * 512 + rt * 32 + rhalf * 16) * T_OUT + t;

    if (interior || t < T_OUT) {     // t even, T_OUT even -> pair fully valid
#pragma unroll
        for (int rl = 0; rl < 16; ++rl) {
            float2 v;
            v.x = src[rl];            // tile[row][rhalf*16 + rl]
            v.y = src[R_PAD + rl];    // tile[row+1][...] (slot s+1 -> t+1)
            *(float2*)o = v;          // STG.64, 8B-aligned
            o += T_OUT;
        }
    }
}

extern "C" void kernel_launch(void* const* d_in, const int* in_sizes, int n_in,
                              void* d_out, int out_size) {
    const float4* x = (const float4*)d_in[0];
    float* out = (float*)d_out;

    dim3 block(32, 8, 1);
    dim3 grid(16, N_TTILES, 16);   // (r tiles of 32, t tiles of 64, bc)
    enframe_kernel<<<grid, block>>>(x, out);
}